// round 16
// baseline (speedup 1.0000x reference)
#include <cuda_runtime.h>
#include <math.h>

#define DT 0.1f
#define EPS_STAT 0.01f

// slot-per-thread fused kernel, time-chunked (TCH via gridDim.y):
//   thread (f, chunk) owns one float4 slot of the row pattern and emits the
//   chunk's rows only. Both chunks run the register recursion redundantly
//   (no barriers -> redundancy is cheap); stores are an unrolled independent
//   coalesced streaming STG.128 burst.
// Row pattern: cb0:(p0x,p0y,s,s) cb1:(0,p1x,p1y,s) cb2:(s,0,p2x,p2y)
//              cb3:(s,s,0,p3x)   cb4:(p3y,s,s,0)
template <int BLOCK, int NEST, int NPRED, int TCH>
__global__ void __launch_bounds__(BLOCK)
kalman_fused(const float* __restrict__ in, float* __restrict__ out,
             const float* __restrict__ sa_p, const float* __restrict__ so_p,
             const float* __restrict__ si_p, int B) {
    __shared__ float4 gt[NEST];    // (K0, K1, s, 0) per est step
    __shared__ float  st[NPRED];   // s per pred row
    __shared__ float  dst_[NPRED]; // s-delta per pred row (dst_[0] = st[0]-s_est_last)

    const int tid = threadIdx.x;

    if (tid == 0) {
        const float sa = *sa_p, so = *so_p, si = *si_p;
        const float g0  = DT * DT * 0.5f;
        const float q00 = sa * sa * (g0 * g0);
        const float q01 = sa * sa * (g0 * DT);
        const float q11 = sa * sa * (DT * DT);
        const float r   = so * so;
        const float eps2 = EPS_STAT * EPS_STAT;
        float P00 = si * si, P01 = 0.0f, P11 = si * si;
        float sprev = 0.0f;
        #pragma unroll
        for (int k = 0; k < NEST; k++) {
            float a = P00 + 2.0f * DT * P01 + DT * DT * P11 + q00;
            float c = P01 + DT * P11 + q01;
            float d = P11 + q11;
            P00 = a; P01 = c; P11 = d;
            float S = P00 + r, rs = 1.0f / S;
            float K0 = P00 * rs, K1 = P01 * rs;
            float omk = 1.0f - K0;
            float A00 = omk * P00;
            float A01 = omk * P01;
            float A10 = P01 - K1 * P00;
            float A11 = P11 - K1 * P01;
            P00 =  A00 * omk      + r * K0 * K0;
            P01 = -A00 * K1 + A01 + r * K0 * K1;
            P11 = -A10 * K1 + A11 + r * K1 * K1;
            sprev = sqrtf(fmaxf(P00, eps2));
            gt[k] = make_float4(K0, K1, sprev, 0.0f);
        }
        #pragma unroll
        for (int j = 0; j < NPRED; j++) {
            float a = P00 + 2.0f * DT * P01 + DT * DT * P11 + q00;
            float c = P01 + DT * P11 + q01;
            float d = P11 + q11;
            P00 = a; P01 = c; P11 = d;
            float s = sqrtf(fmaxf(P00, eps2));
            st[j]   = s;
            dst_[j] = s - sprev;
            sprev = s;
        }
    }
    __syncthreads();

    const int f  = blockIdx.x * BLOCK + tid;
    const int G4 = (B * 5) >> 2;
    if (f >= G4) return;

    constexpr int TOTAL = NEST + NPRED;
    const int chunk = blockIdx.y;
    const int lo = (chunk * TOTAL) / TCH;
    const int hi = ((chunk + 1) * TOTAL) / TCH;

    const int cb = f % 5;
    const int e  = 4 * (f / 5) + ((cb < 3) ? cb : 3);

    float4 pxm, pym, sm;
    switch (cb) {
        case 0: pxm = make_float4(1,0,0,0); pym = make_float4(0,1,0,0); sm = make_float4(0,0,1,1); break;
        case 1: pxm = make_float4(0,1,0,0); pym = make_float4(0,0,1,0); sm = make_float4(0,0,0,1); break;
        case 2: pxm = make_float4(0,0,1,0); pym = make_float4(0,0,0,1); sm = make_float4(1,0,0,0); break;
        case 3: pxm = make_float4(0,0,0,1); pym = make_float4(0,0,0,0); sm = make_float4(1,1,0,0); break;
        default:pxm = make_float4(0,0,0,0); pym = make_float4(1,0,0,0); sm = make_float4(0,1,1,0); break;
    }

    // ---- prefetch ALL measurement rows (independent loads) ----
    const float2* __restrict__ zin = reinterpret_cast<const float2*>(in);
    float2 zr[NEST + 1];
    #pragma unroll
    for (int t = 0; t <= NEST; t++) zr[t] = zin[(size_t)t * B + e];

    // ---- register-only est recursion ----
    float px = zr[0].x, py = zr[0].y;
    float vx = (zr[1].x - zr[0].x) * (1.0f / DT);
    float vy = (zr[1].y - zr[0].y) * (1.0f / DT);

    float rpx[NEST], rpy[NEST];
    #pragma unroll
    for (int t = 0; t < NEST; t++) {
        px += DT * vx;
        py += DT * vy;
        float4 g = gt[t];
        float yx = zr[t + 1].x - px, yy = zr[t + 1].y - py;
        px += g.x * yx; vx += g.y * yx;
        py += g.x * yy; vy += g.y * yy;
        rpx[t] = px; rpy[t] = py;
    }

    float4* __restrict__ out4 = reinterpret_cast<float4*>(out) + f;
    const long long stride = G4;

    // ---- est rows owned by this chunk ----
    #pragma unroll
    for (int t = 0; t < NEST; t++) {
        if (t >= lo && t < hi) {
            const float s = gt[t].z;
            float4 v;
            v.x = fmaf(rpx[t], pxm.x, fmaf(rpy[t], pym.x, s * sm.x));
            v.y = fmaf(rpx[t], pxm.y, fmaf(rpy[t], pym.y, s * sm.y));
            v.z = fmaf(rpx[t], pxm.z, fmaf(rpy[t], pym.z, s * sm.z));
            v.w = fmaf(rpx[t], pxm.w, fmaf(rpy[t], pym.w, s * sm.w));
            __stcs(out4 + (long long)t * stride, v);
        }
    }

    // ---- pred rows owned by this chunk: incremental assembly ----
    const int jp_lo = max(lo, NEST) - NEST;   // first pred index (inclusive)
    const int jp_hi = hi - NEST;              // exclusive
    if (jp_hi <= 0) return;

    const float dx = DT * vx, dy = DT * vy;
    float4 cvec;
    cvec.x = fmaf(dx, pxm.x, dy * pym.x);
    cvec.y = fmaf(dx, pxm.y, dy * pym.y);
    cvec.z = fmaf(dx, pxm.z, dy * pym.z);
    cvec.w = fmaf(dx, pxm.w, dy * pym.w);

    // assemble first owned pred row fully
    float4 v;
    {
        const float tt = (float)(jp_lo + 1) * DT;
        const float qx = fmaf(tt, vx, px);
        const float qy = fmaf(tt, vy, py);
        const float s  = st[jp_lo];
        v.x = fmaf(qx, pxm.x, fmaf(qy, pym.x, s * sm.x));
        v.y = fmaf(qx, pxm.y, fmaf(qy, pym.y, s * sm.y));
        v.z = fmaf(qx, pxm.z, fmaf(qy, pym.z, s * sm.z));
        v.w = fmaf(qx, pxm.w, fmaf(qy, pym.w, s * sm.w));
        __stcs(out4 + (long long)(NEST + jp_lo) * stride, v);
    }
    // remaining rows: 8 ops/row
    #pragma unroll
    for (int j = 0; j < NPRED; j++) {
        if (j > jp_lo && j < jp_hi) {
            const float ds = dst_[j];
            v.x = fmaf(ds, sm.x, v.x + cvec.x);
            v.y = fmaf(ds, sm.y, v.y + cvec.y);
            v.z = fmaf(ds, sm.z, v.z + cvec.z);
            v.w = fmaf(ds, sm.w, v.w + cvec.w);
            __stcs(out4 + (long long)(NEST + j) * stride, v);
        }
    }
}

// generic fallback for unexpected shapes
__global__ void kalman_generic(const float* __restrict__ in, float* __restrict__ out,
                               const float* __restrict__ sa_p, const float* __restrict__ so_p,
                               const float* __restrict__ si_p,
                               int B, int n_est, int n_pred) {
    const int b = blockIdx.x * blockDim.x + threadIdx.x;
    if (b >= B) return;
    const float sa = *sa_p, so = *so_p, si = *si_p;
    const float g0  = DT * DT * 0.5f;
    const float q00 = sa * sa * (g0 * g0);
    const float q01 = sa * sa * (g0 * DT);
    const float q11 = sa * sa * (DT * DT);
    const float r   = so * so;
    const float eps2 = EPS_STAT * EPS_STAT;
    float P00 = si * si, P01 = 0.0f, P11 = si * si;
    const float2* zin = reinterpret_cast<const float2*>(in);
    float2 z0 = zin[b], z1 = zin[(size_t)B + b];
    float px = z0.x, py = z0.y;
    float vx = (z1.x - z0.x) / DT, vy = (z1.y - z0.y) / DT;
    for (int t = 0; t < n_est + n_pred; t++) {
        float a = P00 + 2.0f * DT * P01 + DT * DT * P11 + q00;
        float c = P01 + DT * P11 + q01;
        float d = P11 + q11;
        P00 = a; P01 = c; P11 = d;
        px += DT * vx; py += DT * vy;
        if (t < n_est) {
            float2 z = zin[(size_t)(t + 1) * B + b];
            float S = P00 + r, rs = 1.0f / S;
            float K0 = P00 * rs, K1 = P01 * rs;
            float yx = z.x - px, yy = z.y - py;
            px += K0 * yx; vx += K1 * yx;
            py += K0 * yy; vy += K1 * yy;
            float omk = 1.0f - K0;
            float A00 = omk * P00, A01 = omk * P01;
            float A10 = P01 - K1 * P00, A11 = P11 - K1 * P01;
            P00 =  A00 * omk      + r * K0 * K0;
            P01 = -A00 * K1 + A01 + r * K0 * K1;
            P11 = -A10 * K1 + A11 + r * K1 * K1;
        }
        float s = sqrtf(fmaxf(P00, eps2));
        float* dptr = out + (long long)t * B * 5 + (long long)b * 5;
        dptr[0] = px; dptr[1] = py; dptr[2] = s; dptr[3] = s; dptr[4] = 0.0f;
    }
}

extern "C" void kernel_launch(void* const* d_in, const int* in_sizes, int n_in,
                              void* d_out, int out_size) {
    const float* inputs  = (const float*)d_in[0];
    const float* sigma_a = (const float*)d_in[1];
    const float* sigma_o = (const float*)d_in[2];
    const float* sigma_i = (const float*)d_in[3];

    const int T_OBS = 10;
    const int B = in_sizes[0] / (T_OBS * 2);
    const int n_est = T_OBS - 1;                // 9
    const int totalSteps = out_size / (B * 5);  // 39
    const int n_pred = totalSteps - n_est;      // 30

    if (n_est == 9 && n_pred == 30 && (B % 4) == 0) {
        constexpr int BLOCK = 128;
        constexpr int TCH = 2;
        const int G4 = (B * 5) / 4;
        dim3 grid((G4 + BLOCK - 1) / BLOCK, TCH);
        kalman_fused<BLOCK, 9, 30, TCH><<<grid, BLOCK>>>(
            inputs, (float*)d_out, sigma_a, sigma_o, sigma_i, B);
    } else {
        const int grid = (B + 255) / 256;
        kalman_generic<<<grid, 256>>>(inputs, (float*)d_out,
                                      sigma_a, sigma_o, sigma_i,
                                      B, n_est, n_pred);
    }
}

// round 17
// speedup vs baseline: 1.0279x; 1.0279x over previous
#include <cuda_runtime.h>
#include <math.h>

#define DT 0.1f
#define EPS_STAT 0.01f

// Asymmetric time-chunked slot-per-thread kernel.
//  chunk 0 (rows 0..SPLIT-1): register est recursion (R15 structure)
//  chunk 1 (rows SPLIT..38):  final state via linear weights (no recursion)
// Row pattern: cb0:(p0x,p0y,s,s) cb1:(0,p1x,p1y,s) cb2:(s,0,p2x,p2y)
//              cb3:(s,s,0,p3x)   cb4:(p3y,s,s,0)
template <int BLOCK, int NEST, int NPRED, int SPLIT>
__global__ void __launch_bounds__(BLOCK)
kalman_fused(const float* __restrict__ in, float* __restrict__ out,
             const float* __restrict__ sa_p, const float* __restrict__ so_p,
             const float* __restrict__ si_p, int B) {
    __shared__ float4 gt[NEST];      // (K0, K1, s, 0)
    __shared__ float  dst_[NPRED];   // s-delta per pred row (dst_[0]=st0-s_est_last)
    __shared__ float  s_at_split;    // s of pred row (SPLIT-NEST)
    __shared__ float  wp[NEST + 1];  // final-position weights over z_0..z_9
    __shared__ float  wv[NEST + 1];  // final-velocity weights

    const int tid = threadIdx.x;

    if (tid == 0) {
        const float sa = *sa_p, so = *so_p, si = *si_p;
        const float g0  = DT * DT * 0.5f;
        const float q00 = sa * sa * (g0 * g0);
        const float q01 = sa * sa * (g0 * DT);
        const float q11 = sa * sa * (DT * DT);
        const float r   = so * so;
        const float eps2 = EPS_STAT * EPS_STAT;
        float P00 = si * si, P01 = 0.0f, P11 = si * si;

        // symbolic weights for the final state
        float cp[NEST + 1], cv[NEST + 1];
        #pragma unroll
        for (int i = 0; i <= NEST; i++) { cp[i] = 0.f; cv[i] = 0.f; }
        cp[0] = 1.f;
        cv[0] = -1.0f / DT; cv[1] = 1.0f / DT;

        float sprev = 0.0f;
        #pragma unroll
        for (int k = 0; k < NEST; k++) {
            float a = P00 + 2.0f * DT * P01 + DT * DT * P11 + q00;
            float c = P01 + DT * P11 + q01;
            float d = P11 + q11;
            P00 = a; P01 = c; P11 = d;
            float S = P00 + r, rs = 1.0f / S;
            float K0 = P00 * rs, K1 = P01 * rs;
            float omk = 1.0f - K0;
            float A00 = omk * P00;
            float A01 = omk * P01;
            float A10 = P01 - K1 * P00;
            float A11 = P11 - K1 * P01;
            P00 =  A00 * omk      + r * K0 * K0;
            P01 = -A00 * K1 + A01 + r * K0 * K1;
            P11 = -A10 * K1 + A11 + r * K1 * K1;
            sprev = sqrtf(fmaxf(P00, eps2));
            gt[k] = make_float4(K0, K1, sprev, 0.0f);

            // weight recursion (mirrors the mean recursion)
            #pragma unroll
            for (int i = 0; i <= NEST; i++) {
                float p = cp[i] + DT * cv[i];
                float cy = ((i == k + 1) ? 1.0f : 0.0f) - p;
                cp[i] = p + K0 * cy;
                cv[i] = cv[i] + K1 * cy;
            }
        }
        #pragma unroll
        for (int i = 0; i <= NEST; i++) { wp[i] = cp[i]; wv[i] = cv[i]; }

        #pragma unroll
        for (int j = 0; j < NPRED; j++) {
            float a = P00 + 2.0f * DT * P01 + DT * DT * P11 + q00;
            float c = P01 + DT * P11 + q01;
            float d = P11 + q11;
            P00 = a; P01 = c; P11 = d;
            float s = sqrtf(fmaxf(P00, eps2));
            dst_[j] = s - sprev;
            if (j == SPLIT - NEST) s_at_split = s;
            sprev = s;
        }
    }
    __syncthreads();

    const int f  = blockIdx.x * BLOCK + tid;
    const int G4 = (B * 5) >> 2;
    if (f >= G4) return;

    const int cb = f % 5;
    const int e  = 4 * (f / 5) + ((cb < 3) ? cb : 3);

    float4 pxm, pym, sm;
    switch (cb) {
        case 0: pxm = make_float4(1,0,0,0); pym = make_float4(0,1,0,0); sm = make_float4(0,0,1,1); break;
        case 1: pxm = make_float4(0,1,0,0); pym = make_float4(0,0,1,0); sm = make_float4(0,0,0,1); break;
        case 2: pxm = make_float4(0,0,1,0); pym = make_float4(0,0,0,1); sm = make_float4(1,0,0,0); break;
        case 3: pxm = make_float4(0,0,0,1); pym = make_float4(0,0,0,0); sm = make_float4(1,1,0,0); break;
        default:pxm = make_float4(0,0,0,0); pym = make_float4(1,0,0,0); sm = make_float4(0,1,1,0); break;
    }

    // prefetch all measurement rows (independent loads)
    const float2* __restrict__ zin = reinterpret_cast<const float2*>(in);
    float2 zr[NEST + 1];
    #pragma unroll
    for (int t = 0; t <= NEST; t++) zr[t] = zin[(size_t)t * B + e];

    float4* __restrict__ out4 = reinterpret_cast<float4*>(out) + f;
    const long long stride = G4;

    if (blockIdx.y == 0) {
        // ===== chunk 0: recursion; owns rows [0, SPLIT) =====
        float px = zr[0].x, py = zr[0].y;
        float vx = (zr[1].x - zr[0].x) * (1.0f / DT);
        float vy = (zr[1].y - zr[0].y) * (1.0f / DT);

        float rpx[NEST], rpy[NEST];
        #pragma unroll
        for (int t = 0; t < NEST; t++) {
            px += DT * vx;
            py += DT * vy;
            float4 g = gt[t];
            float yx = zr[t + 1].x - px, yy = zr[t + 1].y - py;
            px += g.x * yx; vx += g.y * yx;
            py += g.x * yy; vy += g.y * yy;
            rpx[t] = px; rpy[t] = py;
        }

        float4 v;
        #pragma unroll
        for (int t = 0; t < NEST; t++) {
            const float s = gt[t].z;
            v.x = fmaf(rpx[t], pxm.x, fmaf(rpy[t], pym.x, s * sm.x));
            v.y = fmaf(rpx[t], pxm.y, fmaf(rpy[t], pym.y, s * sm.y));
            v.z = fmaf(rpx[t], pxm.z, fmaf(rpy[t], pym.z, s * sm.z));
            v.w = fmaf(rpx[t], pxm.w, fmaf(rpy[t], pym.w, s * sm.w));
            __stcs(out4 + (long long)t * stride, v);
        }

        const float dx = DT * vx, dy = DT * vy;
        float4 cvec;
        cvec.x = fmaf(dx, pxm.x, dy * pym.x);
        cvec.y = fmaf(dx, pxm.y, dy * pym.y);
        cvec.z = fmaf(dx, pxm.z, dy * pym.z);
        cvec.w = fmaf(dx, pxm.w, dy * pym.w);

        #pragma unroll
        for (int j = 0; j < SPLIT - NEST; j++) {
            const float ds = dst_[j];
            v.x = fmaf(ds, sm.x, v.x + cvec.x);
            v.y = fmaf(ds, sm.y, v.y + cvec.y);
            v.z = fmaf(ds, sm.z, v.z + cvec.z);
            v.w = fmaf(ds, sm.w, v.w + cvec.w);
            __stcs(out4 + (long long)(NEST + j) * stride, v);
        }
    } else {
        // ===== chunk 1: linear weights (no recursion); owns rows [SPLIT, 39) =====
        float px = 0.f, py = 0.f, vx = 0.f, vy = 0.f;
        #pragma unroll
        for (int t = 0; t <= NEST; t++) {
            const float a = wp[t], b = wv[t];
            px = fmaf(a, zr[t].x, px);
            py = fmaf(a, zr[t].y, py);
            vx = fmaf(b, zr[t].x, vx);
            vy = fmaf(b, zr[t].y, vy);
        }

        constexpr int JP0 = SPLIT - NEST;   // first owned pred index
        const float dx = DT * vx, dy = DT * vy;
        float4 cvec;
        cvec.x = fmaf(dx, pxm.x, dy * pym.x);
        cvec.y = fmaf(dx, pxm.y, dy * pym.y);
        cvec.z = fmaf(dx, pxm.z, dy * pym.z);
        cvec.w = fmaf(dx, pxm.w, dy * pym.w);

        // assemble first owned pred row fully
        float4 v;
        {
            const float tt = (float)(JP0 + 1) * DT;
            const float qx = fmaf(tt, vx, px);
            const float qy = fmaf(tt, vy, py);
            const float s  = s_at_split;
            v.x = fmaf(qx, pxm.x, fmaf(qy, pym.x, s * sm.x));
            v.y = fmaf(qx, pxm.y, fmaf(qy, pym.y, s * sm.y));
            v.z = fmaf(qx, pxm.z, fmaf(qy, pym.z, s * sm.z));
            v.w = fmaf(qx, pxm.w, fmaf(qy, pym.w, s * sm.w));
            __stcs(out4 + (long long)SPLIT * stride, v);
        }
        #pragma unroll
        for (int j = JP0 + 1; j < NPRED; j++) {
            const float ds = dst_[j];
            v.x = fmaf(ds, sm.x, v.x + cvec.x);
            v.y = fmaf(ds, sm.y, v.y + cvec.y);
            v.z = fmaf(ds, sm.z, v.z + cvec.z);
            v.w = fmaf(ds, sm.w, v.w + cvec.w);
            __stcs(out4 + (long long)(NEST + j) * stride, v);
        }
    }
}

// generic fallback for unexpected shapes
__global__ void kalman_generic(const float* __restrict__ in, float* __restrict__ out,
                               const float* __restrict__ sa_p, const float* __restrict__ so_p,
                               const float* __restrict__ si_p,
                               int B, int n_est, int n_pred) {
    const int b = blockIdx.x * blockDim.x + threadIdx.x;
    if (b >= B) return;
    const float sa = *sa_p, so = *so_p, si = *si_p;
    const float g0  = DT * DT * 0.5f;
    const float q00 = sa * sa * (g0 * g0);
    const float q01 = sa * sa * (g0 * DT);
    const float q11 = sa * sa * (DT * DT);
    const float r   = so * so;
    const float eps2 = EPS_STAT * EPS_STAT;
    float P00 = si * si, P01 = 0.0f, P11 = si * si;
    const float2* zin = reinterpret_cast<const float2*>(in);
    float2 z0 = zin[b], z1 = zin[(size_t)B + b];
    float px = z0.x, py = z0.y;
    float vx = (z1.x - z0.x) / DT, vy = (z1.y - z0.y) / DT;
    for (int t = 0; t < n_est + n_pred; t++) {
        float a = P00 + 2.0f * DT * P01 + DT * DT * P11 + q00;
        float c = P01 + DT * P11 + q01;
        float d = P11 + q11;
        P00 = a; P01 = c; P11 = d;
        px += DT * vx; py += DT * vy;
        if (t < n_est) {
            float2 z = zin[(size_t)(t + 1) * B + b];
            float S = P00 + r, rs = 1.0f / S;
            float K0 = P00 * rs, K1 = P01 * rs;
            float yx = z.x - px, yy = z.y - py;
            px += K0 * yx; vx += K1 * yx;
            py += K0 * yy; vy += K1 * yy;
            float omk = 1.0f - K0;
            float A00 = omk * P00, A01 = omk * P01;
            float A10 = P01 - K1 * P00, A11 = P11 - K1 * P01;
            P00 =  A00 * omk      + r * K0 * K0;
            P01 = -A00 * K1 + A01 + r * K0 * K1;
            P11 = -A10 * K1 + A11 + r * K1 * K1;
        }
        float s = sqrtf(fmaxf(P00, eps2));
        float* dptr = out + (long long)t * B * 5 + (long long)b * 5;
        dptr[0] = px; dptr[1] = py; dptr[2] = s; dptr[3] = s; dptr[4] = 0.0f;
    }
}

extern "C" void kernel_launch(void* const* d_in, const int* in_sizes, int n_in,
                              void* d_out, int out_size) {
    const float* inputs  = (const float*)d_in[0];
    const float* sigma_a = (const float*)d_in[1];
    const float* sigma_o = (const float*)d_in[2];
    const float* sigma_i = (const float*)d_in[3];

    const int T_OBS = 10;
    const int B = in_sizes[0] / (T_OBS * 2);
    const int n_est = T_OBS - 1;                // 9
    const int totalSteps = out_size / (B * 5);  // 39
    const int n_pred = totalSteps - n_est;      // 30

    if (n_est == 9 && n_pred == 30 && (B % 4) == 0) {
        constexpr int BLOCK = 128;
        constexpr int SPLIT = 19;   // chunk0: rows 0..18, chunk1: rows 19..38
        const int G4 = (B * 5) / 4;
        dim3 grid((G4 + BLOCK - 1) / BLOCK, 2);
        kalman_fused<BLOCK, 9, 30, SPLIT><<<grid, BLOCK>>>(
            inputs, (float*)d_out, sigma_a, sigma_o, sigma_i, B);
    } else {
        const int grid = (B + 255) / 256;
        kalman_generic<<<grid, 256>>>(inputs, (float*)d_out,
                                      sigma_a, sigma_o, sigma_i,
                                      B, n_est, n_pred);
    }
}